// round 10
// baseline (speedup 1.0000x reference)
#include <cuda_runtime.h>
#include <stdint.h>

#define NCOMP 256
#define PPB   4     // pairs per block
#define TPB   512   // two j-halves x 256 components

__global__ __launch_bounds__(TPB, 2) void clifford_kernel(
    const float* __restrict__ A, const float* __restrict__ B,
    float* __restrict__ out, int npairs)
{
    // 28 KB pool:
    //   [0KB)  As  float4[256]  pairs 0..3 of A at component j
    //   [4KB)  Bp  float4[256]  B positive
    //   [8KB)  Bn  float4[256]  B negated
    //   [12KB) Ssh sign table (8KB)  -- reused as Red after the loop
    //   [20KB) Ish inner table (8KB)
    __shared__ __align__(16) unsigned char pool[28672];
    float4*   As  = reinterpret_cast<float4*>(pool);
    uint32_t* Ssh = reinterpret_cast<uint32_t*>(pool + 12288);
    uint32_t* Ish = reinterpret_cast<uint32_t*>(pool + 20480);
    float4*   Red = reinterpret_cast<float4*>(pool + 12288);

    const int tid  = threadIdx.x;
    const int half = tid >> 8;       // 0: j in [0,128)   1: j in [128,256)
    const int i    = tid & 255;      // output component owned by this thread
    const int p0   = blockIdx.x * PPB;

    // ---- issue gmem loads first (overlap with table build) ----
    // half 0 threads load A rows; half 1 threads load B rows.
    float4 v;
    {
        const float* src = (half ? B : A) + (size_t)p0 * NCOMP + i;
        v.x = src[0 * NCOMP]; v.y = src[1 * NCOMP]; v.z = src[2 * NCOMP]; v.w = src[3 * NCOMP];
    }

    // ---- build sign + inner tables in closed form (4 words each per thread) ----
    {
        const int j   = tid & 255;
        const int h   = (j >> 1) ^ (j >> 2) ^ (j >> 3) ^ (j >> 4) ^ (j >> 5) ^ (j >> 6) ^ (j >> 7);
        const int P1  = __popc(j & h) & 1;
        const int h5  = h >> 5;
        const int jlo = j & 31, jhi = j >> 5;
        uint32_t W = 0;                       // bit L = parity(L & (h & 31))
        if (h & 1)  W ^= 0xAAAAAAAAu;
        if (h & 2)  W ^= 0xCCCCCCCCu;
        if (h & 4)  W ^= 0xF0F0F0F0u;
        if (h & 8)  W ^= 0xFF00FF00u;
        if (h & 16) W ^= 0xFFFF0000u;
        uint32_t Mz = 0xFFFFFFFFu;            // bit L = 1 iff (L & jlo) == 0
        if (jlo & 1)  Mz &= 0x55555555u;
        if (jlo & 2)  Mz &= 0x33333333u;
        if (jlo & 4)  Mz &= 0x0F0F0F0Fu;
        if (jlo & 8)  Mz &= 0x00FF00FFu;
        if (jlo & 16) Mz &= 0x0000FFFFu;
        const int nj = ~jlo & 31;             // bit L = 1 iff L subset of jlo
        uint32_t Ms = 0xFFFFFFFFu;
        if (nj & 1)  Ms &= 0x55555555u;
        if (nj & 2)  Ms &= 0x33333333u;
        if (nj & 4)  Ms &= 0x0F0F0F0Fu;
        if (nj & 8)  Ms &= 0x00FF00FFu;
        if (nj & 16) Ms &= 0x0000FFFFu;
#pragma unroll
        for (int q = 0; q < 4; ++q) {
            const int ihi = (half << 2) + q;
            const int c   = P1 ^ (__popc(ihi & h5) & 1);
            Ssh[(ihi << 8) + j] = c ? ~W : W;
            uint32_t iw = 0;
            if ((jhi & ihi) == 0)      iw |= Mz;   // (j & i) == 0
            if ((ihi & ~jhi & 7) == 0) iw |= Ms;   // i subset of j
            Ish[(ihi << 8) + j] = iw;
        }
    }

    // ---- stage A / B(+) / B(-) ----
    if (half) {
        float4 vn;
        vn.x = -v.x; vn.y = -v.y; vn.z = -v.z; vn.w = -v.w;
        *reinterpret_cast<float4*>(pool + 4096 + i * 16) = v;   // Bp
        *reinterpret_cast<float4*>(pool + 8192 + i * 16) = vn;  // Bn
    } else {
        As[i] = v;
    }
    __syncthreads();

    const int lane  = i & 31;
    const int shamt = 31 - lane;
    const int notI  = (~i) & 255;
    const uint32_t* __restrict__ Srow = Ssh + ((i >> 5) << 8);
    const uint32_t* __restrict__ Irow = Ish + ((i >> 5) << 8);
    const int jbase = half << 7;

    float g0=0.f,g1=0.f,g2=0.f,g3=0.f;   // geometric
    float w0=0.f,w1=0.f,w2=0.f,w3=0.f;   // wedge
    float n0=0.f,n1=0.f,n2=0.f,n3=0.f;   // inner

#pragma unroll 4
    for (int j4 = 0; j4 < 32; ++j4) {
        const int jb = jbase + (j4 << 2);
        const uint4 s4 = *reinterpret_cast<const uint4*>(Srow + jb);
        const uint4 i4 = *reinterpret_cast<const uint4*>(Irow + jb);

#define DO_J(JOFF, SW, ID)                                                      \
        {                                                                       \
            const int      jj  = jb + (JOFF);                                   \
            const int      kx  = jj ^ i;                                        \
            const uint32_t boff = (((int)((SW) << shamt) < 0) ? 8192u : 4096u)  \
                                  + (uint32_t)(kx << 4);                        \
            const bool     wed = ((jj & notI) == 0);                            \
            const bool     inn = ((int)((ID) << shamt) < 0);                    \
            const float4 a = As[jj];                                            \
            const float4 b = *reinterpret_cast<const float4*>(pool + boff);     \
            g0 = fmaf(a.x, b.x, g0); g1 = fmaf(a.y, b.y, g1);                   \
            g2 = fmaf(a.z, b.z, g2); g3 = fmaf(a.w, b.w, g3);                   \
            if (wed) {                                                          \
                w0 = fmaf(a.x, b.x, w0); w1 = fmaf(a.y, b.y, w1);               \
                w2 = fmaf(a.z, b.z, w2); w3 = fmaf(a.w, b.w, w3);               \
            }                                                                   \
            if (inn) {                                                          \
                n0 = fmaf(a.x, b.x, n0); n1 = fmaf(a.y, b.y, n1);               \
                n2 = fmaf(a.z, b.z, n2); n3 = fmaf(a.w, b.w, n3);               \
            }                                                                   \
        }

        DO_J(0, s4.x, i4.x);
        DO_J(1, s4.y, i4.y);
        DO_J(2, s4.z, i4.z);
        DO_J(3, s4.w, i4.w);
#undef DO_J
    }

    // ---- cross-half reduction (Red reuses the sign-table smem) + store ----
    __syncthreads();

    const size_t plane = (size_t)npairs * NCOMP;
    float* __restrict__ og = out + (size_t)p0 * NCOMP + i;

#define ROUND(V0,V1,V2,V3, DST)                                                 \
    {                                                                           \
        if (half) {                                                             \
            Red[i] = make_float4(V0, V1, V2, V3);                               \
        }                                                                       \
        __syncthreads();                                                        \
        if (!half) {                                                            \
            const float4 r = Red[i];                                            \
            (DST)[0 * NCOMP] = V0 + r.x; (DST)[1 * NCOMP] = V1 + r.y;           \
            (DST)[2 * NCOMP] = V2 + r.z; (DST)[3 * NCOMP] = V3 + r.w;           \
        }                                                                       \
        __syncthreads();                                                        \
    }

    ROUND(g0,g1,g2,g3, og)
    ROUND(w0,w1,w2,w3, og + plane)
    ROUND(n0,n1,n2,n3, og + 2 * plane)
#undef ROUND
}

extern "C" void kernel_launch(void* const* d_in, const int* in_sizes, int n_in,
                              void* d_out, int out_size)
{
    const float* A = (const float*)d_in[0];
    const float* B = (const float*)d_in[1];
    float* out = (float*)d_out;

    const int npairs = in_sizes[0] / NCOMP;   // 1024

    clifford_kernel<<<npairs / PPB, TPB>>>(A, B, out, npairs);
}

// round 11
// speedup vs baseline: 1.0942x; 1.0942x over previous
#include <cuda_runtime.h>
#include <stdint.h>

#define NCOMP 256
#define PPB   8      // pairs per block
#define TPB   1024   // four j-quarters x 256 components

__global__ __launch_bounds__(TPB, 1) void clifford_kernel(
    const float* __restrict__ A, const float* __restrict__ B,
    float* __restrict__ out, int npairs)
{
    // 40 KB pool:
    //   [0KB)  As   float4[2][256]  pairs 0..3 / 4..7 of A at component j
    //   [8KB)  Bp   float4[2][256]  B positive
    //   [16KB) Bn   float4[2][256]  B negated
    //   [24KB) Ssh  sign table (8KB)  -- reused as RedA after the loop
    //   [32KB) Ish  inner table (8KB) -- reused as RedB after the loop
    __shared__ __align__(16) unsigned char pool[40960];
    float4*   As   = reinterpret_cast<float4*>(pool);
    uint32_t* Ssh  = reinterpret_cast<uint32_t*>(pool + 24576);
    uint32_t* Ish  = reinterpret_cast<uint32_t*>(pool + 32768);
    float4*   RedA = reinterpret_cast<float4*>(pool + 24576);
    float4*   RedB = reinterpret_cast<float4*>(pool + 32768);

    const int tid = threadIdx.x;
    const int i   = tid & 255;       // output component owned by this thread
    const int q   = tid >> 8;        // j-quarter 0..3
    const int p0  = blockIdx.x * PPB;

    // ---- issue gmem loads first (overlap with table build) ----
    // threads 0-511 stage A (h = q&1 selects pairs 4h..4h+3); 512-1023 stage B.
    float4 v;
    {
        const int    hh  = q & 1;
        const float* src = ((q >> 1) ? B : A) + (size_t)(p0 + 4 * hh) * NCOMP + i;
        v.x = src[0 * NCOMP]; v.y = src[1 * NCOMP]; v.z = src[2 * NCOMP]; v.w = src[3 * NCOMP];
    }

    // ---- build sign + inner tables in closed form (2 words each per thread) ----
    {
        const int j   = i;
        const int h   = (j >> 1) ^ (j >> 2) ^ (j >> 3) ^ (j >> 4) ^ (j >> 5) ^ (j >> 6) ^ (j >> 7);
        const int P1  = __popc(j & h) & 1;
        const int h5  = h >> 5;
        const int jlo = j & 31, jhi = j >> 5;
        uint32_t W = 0;                       // bit L = parity(L & (h & 31))
        if (h & 1)  W ^= 0xAAAAAAAAu;
        if (h & 2)  W ^= 0xCCCCCCCCu;
        if (h & 4)  W ^= 0xF0F0F0F0u;
        if (h & 8)  W ^= 0xFF00FF00u;
        if (h & 16) W ^= 0xFFFF0000u;
        uint32_t Mz = 0xFFFFFFFFu;            // bit L = 1 iff (L & jlo) == 0
        if (jlo & 1)  Mz &= 0x55555555u;
        if (jlo & 2)  Mz &= 0x33333333u;
        if (jlo & 4)  Mz &= 0x0F0F0F0Fu;
        if (jlo & 8)  Mz &= 0x00FF00FFu;
        if (jlo & 16) Mz &= 0x0000FFFFu;
        const int nj = ~jlo & 31;             // bit L = 1 iff L subset of jlo
        uint32_t Ms = 0xFFFFFFFFu;
        if (nj & 1)  Ms &= 0x55555555u;
        if (nj & 2)  Ms &= 0x33333333u;
        if (nj & 4)  Ms &= 0x0F0F0F0Fu;
        if (nj & 8)  Ms &= 0x00FF00FFu;
        if (nj & 16) Ms &= 0x0000FFFFu;
#pragma unroll
        for (int t = 0; t < 2; ++t) {
            const int ihi = q + (t << 2);
            const int c   = P1 ^ (__popc(ihi & h5) & 1);
            Ssh[(ihi << 8) + j] = c ? ~W : W;
            uint32_t iw = 0;
            if ((jhi & ihi) == 0)      iw |= Mz;   // (j & i) == 0
            if ((ihi & ~jhi & 7) == 0) iw |= Ms;   // i subset of j
            Ish[(ihi << 8) + j] = iw;
        }
    }

    // ---- stage A / B(+) / B(-) ----
    {
        const int hh = q & 1;
        if (q >> 1) {
            float4 vn;
            vn.x = -v.x; vn.y = -v.y; vn.z = -v.z; vn.w = -v.w;
            *reinterpret_cast<float4*>(pool + 8192  + hh * 4096 + i * 16) = v;   // Bp
            *reinterpret_cast<float4*>(pool + 16384 + hh * 4096 + i * 16) = vn;  // Bn
        } else {
            As[hh * 256 + i] = v;
        }
    }
    __syncthreads();

    const int lane  = i & 31;
    const int shamt = 31 - lane;
    const int notI  = (~i) & 255;
    const uint32_t* __restrict__ Srow = Ssh + ((i >> 5) << 8);
    const uint32_t* __restrict__ Irow = Ish + ((i >> 5) << 8);
    const int jbase = q << 6;        // 64-wide j-quarter

    float g0=0.f,g1=0.f,g2=0.f,g3=0.f,g4=0.f,g5=0.f,g6=0.f,g7=0.f;   // geometric
    float w0=0.f,w1=0.f,w2=0.f,w3=0.f,w4=0.f,w5=0.f,w6=0.f,w7=0.f;   // wedge
    float n0=0.f,n1=0.f,n2=0.f,n3=0.f,n4=0.f,n5=0.f,n6=0.f,n7=0.f;   // inner

#pragma unroll 2
    for (int j4 = 0; j4 < 16; ++j4) {
        const int jb = jbase + (j4 << 2);
        const uint4 s4 = *reinterpret_cast<const uint4*>(Srow + jb);
        const uint4 i4 = *reinterpret_cast<const uint4*>(Irow + jb);

#define DO_J(JOFF, SW, ID)                                                      \
        {                                                                       \
            const int      jj  = jb + (JOFF);                                   \
            const int      kx  = jj ^ i;                                        \
            const uint32_t boff = (((int)((SW) << shamt) < 0) ? 16384u : 8192u) \
                                  + (uint32_t)(kx << 4);                        \
            const bool     wed = ((jj & notI) == 0);                            \
            const bool     inn = ((int)((ID) << shamt) < 0);                    \
            const float4 a0 = As[jj];                                           \
            const float4 a1 = As[256 + jj];                                     \
            const float4 b0 = *reinterpret_cast<const float4*>(pool + boff);    \
            const float4 b1 = *reinterpret_cast<const float4*>(pool + boff + 4096); \
            g0 = fmaf(a0.x, b0.x, g0); g1 = fmaf(a0.y, b0.y, g1);               \
            g2 = fmaf(a0.z, b0.z, g2); g3 = fmaf(a0.w, b0.w, g3);               \
            g4 = fmaf(a1.x, b1.x, g4); g5 = fmaf(a1.y, b1.y, g5);               \
            g6 = fmaf(a1.z, b1.z, g6); g7 = fmaf(a1.w, b1.w, g7);               \
            if (wed) {                                                          \
                w0 = fmaf(a0.x, b0.x, w0); w1 = fmaf(a0.y, b0.y, w1);           \
                w2 = fmaf(a0.z, b0.z, w2); w3 = fmaf(a0.w, b0.w, w3);           \
                w4 = fmaf(a1.x, b1.x, w4); w5 = fmaf(a1.y, b1.y, w5);           \
                w6 = fmaf(a1.z, b1.z, w6); w7 = fmaf(a1.w, b1.w, w7);           \
            }                                                                   \
            if (inn) {                                                          \
                n0 = fmaf(a0.x, b0.x, n0); n1 = fmaf(a0.y, b0.y, n1);           \
                n2 = fmaf(a0.z, b0.z, n2); n3 = fmaf(a0.w, b0.w, n3);           \
                n4 = fmaf(a1.x, b1.x, n4); n5 = fmaf(a1.y, b1.y, n5);           \
                n6 = fmaf(a1.z, b1.z, n6); n7 = fmaf(a1.w, b1.w, n7);           \
            }                                                                   \
        }

        DO_J(0, s4.x, i4.x);
        DO_J(1, s4.y, i4.y);
        DO_J(2, s4.z, i4.z);
        DO_J(3, s4.w, i4.w);
#undef DO_J
    }

    // ---- 4-quarter reduction tree over the freed table smem + store ----
    __syncthreads();

    const size_t plane = (size_t)npairs * NCOMP;
    float* __restrict__ og = out + (size_t)p0 * NCOMP + i;

#define ROUND(V0,V1,V2,V3,V4,V5,V6,V7, DST)                                     \
    {                                                                           \
        if (q == 1) {                                                           \
            RedA[i * 2 + 0] = make_float4(V0, V1, V2, V3);                      \
            RedA[i * 2 + 1] = make_float4(V4, V5, V6, V7);                      \
        }                                                                       \
        if (q == 3) {                                                           \
            RedB[i * 2 + 0] = make_float4(V0, V1, V2, V3);                      \
            RedB[i * 2 + 1] = make_float4(V4, V5, V6, V7);                      \
        }                                                                       \
        __syncthreads();                                                        \
        if (q == 0) {                                                           \
            const float4 r0 = RedA[i * 2 + 0];                                  \
            const float4 r1 = RedA[i * 2 + 1];                                  \
            V0 += r0.x; V1 += r0.y; V2 += r0.z; V3 += r0.w;                     \
            V4 += r1.x; V5 += r1.y; V6 += r1.z; V7 += r1.w;                     \
        }                                                                       \
        if (q == 2) {                                                           \
            const float4 r0 = RedB[i * 2 + 0];                                  \
            const float4 r1 = RedB[i * 2 + 1];                                  \
            V0 += r0.x; V1 += r0.y; V2 += r0.z; V3 += r0.w;                     \
            V4 += r1.x; V5 += r1.y; V6 += r1.z; V7 += r1.w;                     \
        }                                                                       \
        __syncthreads();                                                        \
        if (q == 2) {                                                           \
            RedA[i * 2 + 0] = make_float4(V0, V1, V2, V3);                      \
            RedA[i * 2 + 1] = make_float4(V4, V5, V6, V7);                      \
        }                                                                       \
        __syncthreads();                                                        \
        if (q == 0) {                                                           \
            const float4 r0 = RedA[i * 2 + 0];                                  \
            const float4 r1 = RedA[i * 2 + 1];                                  \
            (DST)[0 * NCOMP] = V0 + r0.x; (DST)[1 * NCOMP] = V1 + r0.y;         \
            (DST)[2 * NCOMP] = V2 + r0.z; (DST)[3 * NCOMP] = V3 + r0.w;         \
            (DST)[4 * NCOMP] = V4 + r1.x; (DST)[5 * NCOMP] = V5 + r1.y;         \
            (DST)[6 * NCOMP] = V6 + r1.z; (DST)[7 * NCOMP] = V7 + r1.w;         \
        }                                                                       \
        __syncthreads();                                                        \
    }

    ROUND(g0,g1,g2,g3,g4,g5,g6,g7, og)
    ROUND(w0,w1,w2,w3,w4,w5,w6,w7, og + plane)
    ROUND(n0,n1,n2,n3,n4,n5,n6,n7, og + 2 * plane)
#undef ROUND
}

extern "C" void kernel_launch(void* const* d_in, const int* in_sizes, int n_in,
                              void* d_out, int out_size)
{
    const float* A = (const float*)d_in[0];
    const float* B = (const float*)d_in[1];
    float* out = (float*)d_out;

    const int npairs = in_sizes[0] / NCOMP;   // 1024

    clifford_kernel<<<npairs / PPB, TPB>>>(A, B, out, npairs);
}

// round 15
// speedup vs baseline: 1.2162x; 1.1115x over previous
#include <cuda_runtime.h>
#include <stdint.h>

#define NCOMP 256
#define PPB   8     // pairs per block
#define TPB   512   // 128 output-pairs x 4 j-sections

__global__ __launch_bounds__(TPB, 1) void clifford_kernel(
    const float* __restrict__ A, const float* __restrict__ B,
    float* __restrict__ out, int npairs)
{
    // 20 KB pool:
    //   [0KB)  As  float4[2][256]  pairs 0..3 / 4..7 of A at component c
    //   [8KB)  Bp  float4[2][256]  B
    //   [16KB) Ssh 4 rows x 256 sign words (rows ihi=0..3; sign indep of i bit7)
    //   Red reuses [0,16K) after the loop.
    __shared__ __align__(16) unsigned char pool[20480];
    float4*   As4 = reinterpret_cast<float4*>(pool);
    float4*   Bp4 = reinterpret_cast<float4*>(pool + 8192);
    uint32_t* Ssh = reinterpret_cast<uint32_t*>(pool + 16384);
    float4*   RedA = reinterpret_cast<float4*>(pool);
    float4*   RedB = reinterpret_cast<float4*>(pool + 8192);

    const int tid = threadIdx.x;
    const int p0  = blockIdx.x * PPB;

    // ---- gmem loads first (overlap with table build) ----
    float4 va, vb;
    {
        const int c = tid & 255;
        const int g = tid >> 8;
        const float* Ap = A + (size_t)(p0 + 4 * g) * NCOMP + c;
        const float* Bq = B + (size_t)(p0 + 4 * g) * NCOMP + c;
        va.x = Ap[0 * NCOMP]; va.y = Ap[1 * NCOMP]; va.z = Ap[2 * NCOMP]; va.w = Ap[3 * NCOMP];
        vb.x = Bq[0 * NCOMP]; vb.y = Bq[1 * NCOMP]; vb.z = Bq[2 * NCOMP]; vb.w = Bq[3 * NCOMP];
    }

    // ---- build 4-row sign table in closed form (2 words per thread) ----
    {
        const int j  = tid & 255;
        const int h  = (j >> 1) ^ (j >> 2) ^ (j >> 3) ^ (j >> 4) ^ (j >> 5) ^ (j >> 6) ^ (j >> 7);
        const int P1 = __popc(j & h) & 1;
        const int h5 = h >> 5;
        uint32_t W = 0;                       // bit L = parity(L & (h & 31))
        if (h & 1)  W ^= 0xAAAAAAAAu;
        if (h & 2)  W ^= 0xCCCCCCCCu;
        if (h & 4)  W ^= 0xF0F0F0F0u;
        if (h & 8)  W ^= 0xFF00FF00u;
        if (h & 16) W ^= 0xFFFF0000u;
        const int r0 = (tid >> 8) * 2;        // rows {0,1} or {2,3}
#pragma unroll
        for (int t = 0; t < 2; ++t) {
            const int r = r0 + t;
            const int c = P1 ^ (__popc(r & h5) & 1);
            Ssh[(r << 8) + j] = c ? ~W : W;
        }
    }

    // ---- stage A / B ----
    {
        const int c = tid & 255;
        const int g = tid >> 8;
        As4[g * 256 + c] = va;
        Bp4[g * 256 + c] = vb;
    }
    __syncthreads();

    const int io    = tid & 127;     // outputs io and io+128
    const int s     = tid >> 7;      // j-section 0..3
    const int lane  = io & 31;
    const int shamt = 31 - lane;
    const int ihi   = io >> 5;       // 0..3, warp-uniform
    const uint32_t* __restrict__ Srow = Ssh + (ihi << 8);
    const int jb0 = s << 5;          // j in [jb0, jb0+32), partners +128

    float4 Ga0 = {0,0,0,0}, Ga1 = {0,0,0,0}, Gb0 = {0,0,0,0}, Gb1 = {0,0,0,0};
    float4 Wa0 = {0,0,0,0}, Wa1 = {0,0,0,0}, Wb0 = {0,0,0,0}, Wb1 = {0,0,0,0};
    float4 Na0 = {0,0,0,0}, Na1 = {0,0,0,0}, Nb0 = {0,0,0,0}, Nb1 = {0,0,0,0};

#define XS(v, m)                                                                \
    v.x = __uint_as_float(__float_as_uint(v.x) ^ (m));                          \
    v.y = __uint_as_float(__float_as_uint(v.y) ^ (m));                          \
    v.z = __uint_as_float(__float_as_uint(v.z) ^ (m));                          \
    v.w = __uint_as_float(__float_as_uint(v.w) ^ (m));
#define FMA4(acc, a, b)                                                         \
    acc.x = fmaf(a.x, b.x, acc.x); acc.y = fmaf(a.y, b.y, acc.y);               \
    acc.z = fmaf(a.z, b.z, acc.z); acc.w = fmaf(a.w, b.w, acc.w);

#define STEP(O, SW1, SW2)                                                       \
    {                                                                           \
        const int j  = jq + (O);             /* j < 128 */                      \
        const int kx = j ^ io;               /* < 128 */                        \
        const uint32_t sm1 = ((SW1) << shamt) & 0x80000000u;                    \
        const uint32_t sm2 = ((SW2) << shamt) & 0x80000000u;                    \
        float4 a10 = As4[j];        float4 a11 = As4[256 + j];                  \
        float4 a20 = As4[j + 128];  float4 a21 = As4[384 + j];                  \
        XS(a10, sm1) XS(a11, sm1) XS(a20, sm2) XS(a21, sm2)                     \
        const float4 b10 = Bp4[kx];        const float4 b11 = Bp4[256 + kx];    \
        const float4 b20 = Bp4[kx + 128];  const float4 b21 = Bp4[384 + kx];    \
        const bool wed = ((j & ~io & 127) == 0);                                \
        const bool Z   = ((j & io) == 0);                                       \
        const bool S   = ((io & ~j & 127) == 0);                                \
        const bool zs  = Z | S;                                                 \
        FMA4(Ga0, a10, b10) FMA4(Ga1, a11, b11)                                 \
        FMA4(Ga0, a20, b20) FMA4(Ga1, a21, b21)                                 \
        FMA4(Gb0, a10, b20) FMA4(Gb1, a11, b21)                                 \
        FMA4(Gb0, a20, b10) FMA4(Gb1, a21, b11)                                 \
        if (wed) {                                                              \
            FMA4(Wa0, a10, b10) FMA4(Wa1, a11, b11)                             \
            FMA4(Wb0, a10, b20) FMA4(Wb1, a11, b21)                             \
            FMA4(Wb0, a20, b10) FMA4(Wb1, a21, b11)                             \
        }                                                                       \
        if (zs) {                                                               \
            FMA4(Na0, a10, b10) FMA4(Na1, a11, b11)                             \
            FMA4(Na0, a20, b20) FMA4(Na1, a21, b21)                             \
        }                                                                       \
        if (Z) { FMA4(Nb0, a10, b20) FMA4(Nb1, a11, b21) }                      \
        if (S) { FMA4(Nb0, a20, b10) FMA4(Nb1, a21, b11) }                      \
    }

#pragma unroll 2
    for (int t4 = 0; t4 < 8; ++t4) {
        const int jq = jb0 + (t4 << 2);
        const uint4 sA = *reinterpret_cast<const uint4*>(Srow + jq);        // sign(j, .)
        const uint4 sB = *reinterpret_cast<const uint4*>(Srow + jq + 128);  // sign(j+128, .)
        STEP(0, sA.x, sB.x)
        STEP(1, sA.y, sB.y)
        STEP(2, sA.z, sB.z)
        STEP(3, sA.w, sB.w)
    }
#undef STEP
#undef XS

    // ---- 4-section reduction over reused pool + store ----
    __syncthreads();

    const size_t plane = (size_t)npairs * NCOMP;
    float* __restrict__ obase = out + (size_t)p0 * NCOMP + io;

#define ADD4(d, r) d.x += r.x; d.y += r.y; d.z += r.z; d.w += r.w;
#define ROUND(Pa0, Pa1, Pb0, Pb1, PROD)                                         \
    {                                                                           \
        if (s == 1) {                                                           \
            RedA[io*4+0] = Pa0; RedA[io*4+1] = Pa1;                             \
            RedA[io*4+2] = Pb0; RedA[io*4+3] = Pb1;                             \
        }                                                                       \
        if (s == 3) {                                                           \
            RedB[io*4+0] = Pa0; RedB[io*4+1] = Pa1;                             \
            RedB[io*4+2] = Pb0; RedB[io*4+3] = Pb1;                             \
        }                                                                       \
        __syncthreads();                                                        \
        if (s == 0) {                                                           \
            float4 r;                                                           \
            r = RedA[io*4+0]; ADD4(Pa0, r) r = RedA[io*4+1]; ADD4(Pa1, r)       \
            r = RedA[io*4+2]; ADD4(Pb0, r) r = RedA[io*4+3]; ADD4(Pb1, r)       \
        }                                                                       \
        if (s == 2) {                                                           \
            float4 r;                                                           \
            r = RedB[io*4+0]; ADD4(Pa0, r) r = RedB[io*4+1]; ADD4(Pa1, r)       \
            r = RedB[io*4+2]; ADD4(Pb0, r) r = RedB[io*4+3]; ADD4(Pb1, r)       \
        }                                                                       \
        __syncthreads();                                                        \
        if (s == 2) {                                                           \
            RedA[io*4+0] = Pa0; RedA[io*4+1] = Pa1;                             \
            RedA[io*4+2] = Pb0; RedA[io*4+3] = Pb1;                             \
        }                                                                       \
        __syncthreads();                                                        \
        if (s == 0) {                                                           \
            float4 r;                                                           \
            r = RedA[io*4+0]; ADD4(Pa0, r) r = RedA[io*4+1]; ADD4(Pa1, r)       \
            r = RedA[io*4+2]; ADD4(Pb0, r) r = RedA[io*4+3]; ADD4(Pb1, r)       \
            float* d = obase + (PROD) * plane;                                  \
            d[0*NCOMP] = Pa0.x; d[1*NCOMP] = Pa0.y;                             \
            d[2*NCOMP] = Pa0.z; d[3*NCOMP] = Pa0.w;                             \
            d[4*NCOMP] = Pa1.x; d[5*NCOMP] = Pa1.y;                             \
            d[6*NCOMP] = Pa1.z; d[7*NCOMP] = Pa1.w;                             \
            float* d2 = d + 128;                                                \
            d2[0*NCOMP] = Pb0.x; d2[1*NCOMP] = Pb0.y;                           \
            d2[2*NCOMP] = Pb0.z; d2[3*NCOMP] = Pb0.w;                           \
            d2[4*NCOMP] = Pb1.x; d2[5*NCOMP] = Pb1.y;                           \
            d2[6*NCOMP] = Pb1.z; d2[7*NCOMP] = Pb1.w;                           \
        }                                                                       \
        __syncthreads();                                                        \
    }

    ROUND(Ga0, Ga1, Gb0, Gb1, 0)
    ROUND(Wa0, Wa1, Wb0, Wb1, 1)
    ROUND(Na0, Na1, Nb0, Nb1, 2)
#undef ROUND
#undef ADD4
#undef FMA4
}

extern "C" void kernel_launch(void* const* d_in, const int* in_sizes, int n_in,
                              void* d_out, int out_size)
{
    const float* A = (const float*)d_in[0];
    const float* B = (const float*)d_in[1];
    float* out = (float*)d_out;

    const int npairs = in_sizes[0] / NCOMP;   // 1024

    clifford_kernel<<<npairs / PPB, TPB>>>(A, B, out, npairs);
}